// round 14
// baseline (speedup 1.0000x reference)
#include <cuda_runtime.h>
#include <cuda_bf16.h>
#include <math.h>
#include <stdint.h>

// ---------------- problem constants ----------------
#define NS     4
#define NBATCH 32
#define NCIN   128
#define NCOUT  256
#define HH     16
#define WW     16
#define DDIM   1152
#define NPIX   256
#define NCOLS  8192
#define NB32   36          // 32-wide blocks per dim
#define DD2    (DDIM * DDIM)
#define DR     (DDIM * NCOUT)
#define NCTA   148
#define NWARPS (NCTA * 8)

// ---------------- scratch ----------------
__device__ __nv_bfloat16 g_Phi[(size_t)NS * DDIM * NCOLS];
__device__ __nv_bfloat16 g_Plo[(size_t)NS * DDIM * NCOLS];
__device__ __nv_bfloat16 g_Yhi[(size_t)NCOUT * NCOLS];
__device__ __nv_bfloat16 g_Ylo[(size_t)NCOUT * NCOLS];
__device__ float g_prec[(size_t)NS * DD2];
__device__ float g_M   [(size_t)NS * DD2];   // explicit block lower inverse of L (32-blocked)
__device__ float g_S   [(size_t)NS * DD2];   // substitution accumulators
__device__ float g_R   [(size_t)NS * DR];
__device__ float g_T   [(size_t)NS * DR];
__device__ float g_logdet_part[NS * NB32];
__device__ float g_part[NS * 1152];
__device__ unsigned g_flags[NCTA];           // grid-barrier arrival flags (monotonic gens)
__device__ unsigned g_release;               // grid-barrier release gen

// ---------------- helpers ----------------
__device__ __forceinline__ uint32_t smem_u32(const void* p) {
    uint32_t a;
    asm("{ .reg .u64 t; cvta.to.shared.u64 t, %1; cvt.u32.u64 %0, t; }" : "=r"(a) : "l"(p));
    return a;
}

#define CP_ASYNC16(dst, src) \
    asm volatile("cp.async.cg.shared.global [%0], [%1], 16;" :: "r"(dst), "l"(src) : "memory")
#define CP_COMMIT() asm volatile("cp.async.commit_group;" ::: "memory")
#define CP_WAIT1()  asm volatile("cp.async.wait_group 1;" ::: "memory")

#define LDMATRIX_X4(r0, r1, r2, r3, addr) \
    asm volatile("ldmatrix.sync.aligned.m8n8.x4.shared.b16 {%0,%1,%2,%3}, [%4];" \
        : "=r"(r0), "=r"(r1), "=r"(r2), "=r"(r3) : "r"(addr))

#define MMA16816(d, a, b0, b1) \
    asm volatile("mma.sync.aligned.m16n8k16.row.col.f32.bf16.bf16.f32 " \
        "{%0,%1,%2,%3}, {%4,%5,%6,%7}, {%8,%9}, {%0,%1,%2,%3};" \
        : "+f"((d)[0]), "+f"((d)[1]), "+f"((d)[2]), "+f"((d)[3]) \
        : "r"((a)[0]), "r"((a)[1]), "r"((a)[2]), "r"((a)[3]), "r"(b0), "r"(b1))

__device__ __forceinline__ uint32_t sw128(uint32_t off) {
    return off ^ ((off >> 3) & 0x70);
}

// ---------------- patch build (bf16 hi/lo) ----------------
__global__ __launch_bounds__(256) void build_patches(const float* __restrict__ X,
                                                     const float* __restrict__ lp) {
    size_t i = (size_t)blockIdx.x * 256 + threadIdx.x;
    int n = (int)(i % NCOLS);
    size_t r = i / NCOLS;
    int d = (int)(r % DDIM);
    int s = (int)(r / DDIM);
    int b = n >> 8;
    int p = n & 255;
    int y = p >> 4, x = p & 15;
    int cin = d / 9;
    int rem = d - cin * 9;
    int kh = rem / 3, kw = rem - kh * 3;
    int yy = y + kh - 1, xx = x + kw - 1;
    float v = 0.0f;
    if (yy >= 0 && yy < HH && xx >= 0 && xx < WW) {
        float sp = expf(0.5f * lp[b]);
        v = sp * X[((((size_t)s * NBATCH + b) * NCIN + cin) * HH + yy) * WW + xx];
    }
    __nv_bfloat16 hi = __float2bfloat16_rn(v);
    g_Phi[i] = hi;
    g_Plo[i] = __float2bfloat16_rn(v - __bfloat162float(hi));
}

__global__ __launch_bounds__(256) void build_yt(const float* __restrict__ u,
                                                const float* __restrict__ lp) {
    size_t i = (size_t)blockIdx.x * 256 + threadIdx.x;
    int n = (int)(i % NCOLS);
    int c = (int)(i / NCOLS);
    int b = n >> 8;
    int p = n & 255;
    float v = expf(0.5f * lp[b]) * u[((size_t)b * NCOUT + c) * NPIX + p];
    __nv_bfloat16 hi = __float2bfloat16_rn(v);
    g_Yhi[i] = hi;
    g_Ylo[i] = __float2bfloat16_rn(v - __bfloat162float(hi));
}

// zero S and M (M's untouched upper blocks must be 0 for the dense solves)
__global__ __launch_bounds__(256) void zero_ms_kernel() {
    size_t i = (size_t)blockIdx.x * 256 + threadIdx.x;
    float4 z = make_float4(0.f, 0.f, 0.f, 0.f);
    ((float4*)g_S)[i] = z;
    ((float4*)g_M)[i] = z;
}

// ---------------- warp-MMA Gram kernel (R10 config: K-chunk 64, 1 CTA/SM) ----------------
#define TILE_B 16384
#define BUF_B  65536
#define GRAM_SMEM (2 * BUF_B)

__global__ __launch_bounds__(256, 1) void tc_gram_kernel() {
    extern __shared__ char sm[];
    uint32_t smb = smem_u32(sm);
    int tid = threadIdx.x;
    int wid = tid >> 5, lid = tid & 31;
    int s = blockIdx.y;
    int t = blockIdx.x;

    const __nv_bfloat16 *Ah, *Al, *Bh, *Bl;
    float* C;
    int ldc;
    float prior;
    if (t < 45) {
        int bi = 0;
        while ((bi + 1) * (bi + 2) / 2 <= t) bi++;
        int bj = t - bi * (bi + 1) / 2;
        size_t ar = (size_t)(s * DDIM + bi * 128) * NCOLS;
        size_t br = (size_t)(s * DDIM + bj * 128) * NCOLS;
        Ah = g_Phi + ar; Al = g_Plo + ar;
        Bh = g_Phi + br; Bl = g_Plo + br;
        C = g_prec + (size_t)s * DD2 + (size_t)bi * 128 * DDIM + bj * 128;
        ldc = DDIM;
        prior = (bi == bj) ? 1.0f : 0.0f;
    } else {
        int u2 = t - 45;
        int bi = u2 >> 1, bj = u2 & 1;
        size_t ar = (size_t)(s * DDIM + bi * 128) * NCOLS;
        size_t br = (size_t)bj * 128 * NCOLS;
        Ah = g_Phi + ar; Al = g_Plo + ar;
        Bh = g_Yhi + br; Bl = g_Ylo + br;
        C = g_R + (size_t)s * DR + (size_t)bi * 128 * NCOUT + bj * 128;
        ldc = NCOUT;
        prior = 0.0f;
    }

    int lrow[4], lseg[4];
    uint32_t lsw[4];
#pragma unroll
    for (int j = 0; j < 4; j++) {
        int idx = tid + j * 256;
        lrow[j] = idx >> 3;
        lseg[j] = idx & 7;
        lsw[j] = sw128((uint32_t)(lrow[j] * 128 + lseg[j] * 16));
    }

    float acc[2][8][4];
#pragma unroll
    for (int a = 0; a < 2; a++)
#pragma unroll
        for (int b = 0; b < 8; b++)
#pragma unroll
            for (int c = 0; c < 4; c++) acc[a][b][c] = 0.0f;

    int wm = (wid >> 1) * 32;
    int wn = (wid & 1) * 64;
    int l16 = lid & 15;
    int kseg16 = (lid >> 4) * 16;

    {
#pragma unroll
        for (int arr = 0; arr < 4; arr++) {
            const __nv_bfloat16* G = (arr == 0) ? Ah : (arr == 1) ? Al : (arr == 2) ? Bh : Bl;
#pragma unroll
            for (int j = 0; j < 4; j++)
                CP_ASYNC16(smb + arr * TILE_B + lsw[j],
                           G + (size_t)lrow[j] * NCOLS + lseg[j] * 8);
        }
        CP_COMMIT();
    }

    for (int i = 0; i < 128; i++) {
        int buf = i & 1;
        if (i + 1 < 128) {
            int k0 = (i + 1) * 64;
            uint32_t bb = smb + ((i + 1) & 1) * BUF_B;
#pragma unroll
            for (int arr = 0; arr < 4; arr++) {
                const __nv_bfloat16* G = (arr == 0) ? Ah : (arr == 1) ? Al : (arr == 2) ? Bh : Bl;
#pragma unroll
                for (int j = 0; j < 4; j++)
                    CP_ASYNC16(bb + arr * TILE_B + lsw[j],
                               G + (size_t)lrow[j] * NCOLS + k0 + lseg[j] * 8);
            }
        }
        CP_COMMIT();
        CP_WAIT1();
        __syncthreads();

        uint32_t base = smb + buf * BUF_B;
#pragma unroll
        for (int ks = 0; ks < 4; ks++) {
            int kb = ks * 32 + kseg16;
            uint32_t ah[2][4], al[2][4], bh[4][4], bl[4][4];
#pragma unroll
            for (int mb = 0; mb < 2; mb++) {
                uint32_t off = sw128((uint32_t)((wm + mb * 16 + l16) * 128 + kb));
                LDMATRIX_X4(ah[mb][0], ah[mb][1], ah[mb][2], ah[mb][3], base + off);
                LDMATRIX_X4(al[mb][0], al[mb][1], al[mb][2], al[mb][3], base + TILE_B + off);
            }
#pragma unroll
            for (int nb = 0; nb < 4; nb++) {
                uint32_t off = sw128((uint32_t)((wn + nb * 16 + l16) * 128 + kb));
                LDMATRIX_X4(bh[nb][0], bh[nb][1], bh[nb][2], bh[nb][3], base + 2 * TILE_B + off);
                LDMATRIX_X4(bl[nb][0], bl[nb][1], bl[nb][2], bl[nb][3], base + 3 * TILE_B + off);
            }
#pragma unroll
            for (int mb = 0; mb < 2; mb++)
#pragma unroll
                for (int n8 = 0; n8 < 8; n8++) {
                    int nb = n8 >> 1, h = n8 & 1;
                    MMA16816(acc[mb][n8], ah[mb], bh[nb][h], bh[nb][h + 2]);
                    MMA16816(acc[mb][n8], ah[mb], bl[nb][h], bl[nb][h + 2]);
                    MMA16816(acc[mb][n8], al[mb], bh[nb][h], bh[nb][h + 2]);
                }
        }
        __syncthreads();
    }

    int tq = lid >> 2;
    int tc2 = (lid & 3) * 2;
#pragma unroll
    for (int mb = 0; mb < 2; mb++) {
#pragma unroll
        for (int n8 = 0; n8 < 8; n8++) {
            int col = wn + n8 * 8 + tc2;
            int row0 = wm + mb * 16 + tq;
            int row1 = row0 + 8;
            float c0 = acc[mb][n8][0], c1 = acc[mb][n8][1];
            float c2 = acc[mb][n8][2], c3 = acc[mb][n8][3];
            if (prior != 0.0f) {
                if (row0 == col) c0 += prior;
                if (row0 == col + 1) c1 += prior;
                if (row1 == col) c2 += prior;
                if (row1 == col + 1) c3 += prior;
            }
            *(float2*)&C[(size_t)row0 * ldc + col] = make_float2(c0, c1);
            *(float2*)&C[(size_t)row1 * ldc + col] = make_float2(c2, c3);
        }
    }
}

// ---------------- persistent fused Cholesky + block inverse (32-blocked) ----------------
// grid barrier: flag-array + poller, monotonic generations (replay-safe).
__device__ __forceinline__ void grid_barrier(unsigned gen) {
    __threadfence();
    __syncthreads();
    if (threadIdx.x == 0)
        ((volatile unsigned*)g_flags)[blockIdx.x] = gen;
    if (blockIdx.x == 0) {
        if (threadIdx.x < 32) {
            for (int i = threadIdx.x; i < NCTA; i += 32)
                while (((volatile unsigned*)g_flags)[i] < gen) {}
        }
        __syncthreads();
        __threadfence();
        if (threadIdx.x == 0)
            *((volatile unsigned*)&g_release) = gen;
    }
    if (threadIdx.x == 0)
        while (*((volatile unsigned*)&g_release) < gen) {}
    __syncthreads();
    __threadfence();
}

// warp-level 32x32x32 GEMM: C = alpha * A @ opB(B) (+ C if beta).
// A,B,C global (ld = DDIM); As/Bs per-warp smem staging [32*33].
__device__ __forceinline__ void wgemm32(const float* __restrict__ A,
                                        const float* __restrict__ B,
                                        float* __restrict__ C,
                                        int TB, float alpha, int beta,
                                        float* As_, float* Bs_, int lane) {
    {
        const float4* ar = (const float4*)(A + (size_t)lane * DDIM);
        const float4* br = (const float4*)(B + (size_t)lane * DDIM);
#pragma unroll
        for (int q = 0; q < 8; q++) {
            float4 va = __ldcg(ar + q);
            float4 vb = __ldcg(br + q);
            As_[lane * 33 + q * 4 + 0] = va.x; As_[lane * 33 + q * 4 + 1] = va.y;
            As_[lane * 33 + q * 4 + 2] = va.z; As_[lane * 33 + q * 4 + 3] = va.w;
            Bs_[lane * 33 + q * 4 + 0] = vb.x; Bs_[lane * 33 + q * 4 + 1] = vb.y;
            Bs_[lane * 33 + q * 4 + 2] = vb.z; Bs_[lane * 33 + q * 4 + 3] = vb.w;
        }
    }
    __syncwarp();
    float acc[32];
#pragma unroll
    for (int r = 0; r < 32; r++) acc[r] = 0.0f;
    if (TB) {
#pragma unroll 4
        for (int k = 0; k < 32; k++) {
            float bv = Bs_[lane * 33 + k];          // B[c][k]  (B^T)
#pragma unroll
            for (int r = 0; r < 32; r++)
                acc[r] = fmaf(As_[r * 33 + k], bv, acc[r]);
        }
    } else {
#pragma unroll 4
        for (int k = 0; k < 32; k++) {
            float bv = Bs_[k * 33 + lane];          // B[k][c]
#pragma unroll
            for (int r = 0; r < 32; r++)
                acc[r] = fmaf(As_[r * 33 + k], bv, acc[r]);
        }
    }
#pragma unroll 4
    for (int r = 0; r < 32; r++) {
        float v = alpha * acc[r];
        if (beta) v += __ldcg(C + (size_t)r * DDIM + lane);
        C[(size_t)r * DDIM + lane] = v;
    }
    __syncwarp();
}

__global__ __launch_bounds__(256) void chol_fused_kernel() {
    extern __shared__ float shm[];
    int tid = threadIdx.x, wid = tid >> 5, lid = tid & 31;
    int gwarp = blockIdx.x * 8 + wid;
    float* As = shm + wid * 2 * 32 * 33;
    float* Bs = As + 32 * 33;
    unsigned gen = *((volatile unsigned*)&g_release);

#pragma unroll 1
    for (int t = 0; t < NB32; t++) {
        // ---- phase A: factor + invert the 32x32 diag block (one warp per s) ----
        if (gwarp < NS) {
            int s = gwarp;
            float* Pd = g_prec + (size_t)s * DD2 + (size_t)(t * 32) * DDIM + t * 32;
            int r = lid;
            float row[32];
#pragma unroll
            for (int q = 0; q < 8; q++) {
                float4 v = __ldcg((const float4*)(Pd + (size_t)r * DDIM + q * 4));
                row[q * 4 + 0] = v.x; row[q * 4 + 1] = v.y;
                row[q * 4 + 2] = v.z; row[q * 4 + 3] = v.w;
            }
            float myd = 1.0f;
#pragma unroll
            for (int j = 0; j < 32; j++) {
                float d = __shfl_sync(0xffffffffu, row[j], j);
                float ljj = sqrtf(d);
                float inv = 1.0f / ljj;
                if (r == j) myd = ljj;
                row[j] = (r == j) ? ljj : ((r > j) ? row[j] * inv : row[j]);
                float lrj = row[j];
#pragma unroll
                for (int c = j + 1; c < 32; c++) {
                    float lcj = __shfl_sync(0xffffffffu, row[j], c);
                    if (r >= c) row[c] -= lrj * lcj;
                }
            }
#pragma unroll
            for (int q = 0; q < 8; q++)
                *((float4*)(Pd + (size_t)r * DDIM + q * 4)) =
                    make_float4(row[q * 4], row[q * 4 + 1], row[q * 4 + 2], row[q * 4 + 3]);
            // triangular inverse: lane = column c
            int c = r;
            float x[32];
#pragma unroll
            for (int i = 0; i < 32; i++) {
                float a2 = (i == c) ? 1.0f : 0.0f;
#pragma unroll
                for (int tt = 0; tt < i; tt++) {
                    float lit = __shfl_sync(0xffffffffu, row[tt], i);
                    a2 -= lit * x[tt];
                }
                float lii = __shfl_sync(0xffffffffu, row[i], i);
                x[i] = a2 * (1.0f / lii);
            }
            float* Md = g_M + (size_t)s * DD2 + (size_t)(t * 32) * DDIM + t * 32;
#pragma unroll
            for (int i = 0; i < 32; i++)
                Md[(size_t)i * DDIM + c] = x[i];
            float lv = 2.0f * logf(myd);
#pragma unroll
            for (int o = 16; o; o >>= 1) lv += __shfl_xor_sync(0xffffffffu, lv, o);
            if (lid == 0) g_logdet_part[s * NB32 + t] = lv;
        }
        grid_barrier(++gen);

        // ---- phase B: TRSM panels + M column t (35 tiles per s) ----
        {
            int rem = NB32 - 1 - t;
            for (int tile = gwarp; tile < NS * 35; tile += NWARPS) {
                int s = tile / 35;
                int j = tile % 35;
                float* P = g_prec + (size_t)s * DD2;
                float* M = g_M + (size_t)s * DD2;
                const float* Mtt = M + (size_t)(t * 32) * DDIM + t * 32;
                if (j < rem) {
                    int i = t + 1 + j;
                    float* Pit = P + (size_t)(i * 32) * DDIM + t * 32;
                    wgemm32(Pit, Mtt, Pit, 1, 1.0f, 0, As, Bs, lid);  // L_it = P_it @ inv^T
                } else {
                    int k = j - rem;  // 0..t-1
                    const float* Stk = g_S + (size_t)s * DD2 + (size_t)(t * 32) * DDIM + k * 32;
                    float* Mtk = M + (size_t)(t * 32) * DDIM + k * 32;
                    wgemm32(Mtt, Stk, Mtk, 0, -1.0f, 0, As, Bs, lid);  // M_tk = -inv @ S_tk
                }
            }
        }
        grid_barrier(++gen);

        // ---- phase C: SYRK trailing + S accumulation ----
        {
            int rem = NB32 - 1 - t;
            int ntri = rem * (rem + 1) / 2;
            int per_s = ntri + rem * (t + 1);
            for (int tile = gwarp; tile < NS * per_s; tile += NWARPS) {
                int s = tile / per_s;
                int m = tile % per_s;
                float* P = g_prec + (size_t)s * DD2;
                if (m < ntri) {
                    int a = 0;
                    while ((a + 1) * (a + 2) / 2 <= m) a++;
                    int b = m - a * (a + 1) / 2;
                    int i = t + 1 + a, j2 = t + 1 + b;
                    wgemm32(P + (size_t)(i * 32) * DDIM + t * 32,
                            P + (size_t)(j2 * 32) * DDIM + t * 32,
                            P + (size_t)(i * 32) * DDIM + j2 * 32,
                            1, -1.0f, 1, As, Bs, lid);          // P_ij -= L_it @ L_jt^T
                } else {
                    int e = m - ntri;
                    int i = t + 1 + e / (t + 1);
                    int k = e % (t + 1);
                    wgemm32(P + (size_t)(i * 32) * DDIM + t * 32,
                            g_M + (size_t)s * DD2 + (size_t)(t * 32) * DDIM + k * 32,
                            g_S + (size_t)s * DD2 + (size_t)(i * 32) * DDIM + k * 32,
                            0, 1.0f, 1, As, Bs, lid);           // S_ik += L_it @ M_tk
                }
            }
        }
        grid_barrier(++gen);
    }
}

// ---------------- fp32 128x64 GEMM for the dense solves ----------------
template <int TA>
__device__ __forceinline__ void gemmK64(const float* __restrict__ A, int lda,
                                        const float* __restrict__ Bp, int ldb,
                                        float* __restrict__ C, int ldc,
                                        int Kdim, const float* __restrict__ Zp) {
    __shared__ float As[16][128];
    __shared__ float Bs[16][64];
    float acc[8][4];
#pragma unroll
    for (int a = 0; a < 8; a++)
#pragma unroll
        for (int b = 0; b < 4; b++) acc[a][b] = 0.0f;
    int tid = threadIdx.x;
    int tr = tid >> 4, tc = tid & 15;

    for (int k0 = 0; k0 < Kdim; k0 += 16) {
#pragma unroll
        for (int q = 0; q < 2; q++) {
            int idx = tid + q * 256;
            if (TA) {
                int kk = idx >> 5, m4 = (idx & 31) << 2;
                float4 v = *(const float4*)&A[(size_t)(k0 + kk) * lda + m4];
                *(float4*)&As[kk][m4] = v;
            } else {
                int rr = idx >> 2, c4 = (idx & 3) << 2;
                float4 v = *(const float4*)&A[(size_t)rr * lda + k0 + c4];
                As[c4 + 0][rr] = v.x; As[c4 + 1][rr] = v.y;
                As[c4 + 2][rr] = v.z; As[c4 + 3][rr] = v.w;
            }
        }
        {
            int kk = tid >> 4, n4 = (tid & 15) << 2;
            float4 v = *(const float4*)&Bp[(size_t)(k0 + kk) * ldb + n4];
            *(float4*)&Bs[kk][n4] = v;
        }
        __syncthreads();
#pragma unroll
        for (int kk = 0; kk < 16; kk++) {
            float ra[8], rb[4];
            *(float4*)&ra[0] = *(const float4*)&As[kk][tr * 8];
            *(float4*)&ra[4] = *(const float4*)&As[kk][tr * 8 + 4];
            *(float4*)&rb[0] = *(const float4*)&Bs[kk][tc * 4];
#pragma unroll
            for (int a = 0; a < 8; a++)
#pragma unroll
                for (int b = 0; b < 4; b++)
                    acc[a][b] = fmaf(ra[a], rb[b], acc[a][b]);
        }
        __syncthreads();
    }
#pragma unroll
    for (int a = 0; a < 8; a++) {
        int row = tr * 8 + a;
        float4 v = make_float4(acc[a][0], acc[a][1], acc[a][2], acc[a][3]);
        if (Zp) {
            int col = tc * 4;
            v.x += Zp[(size_t)(col + 0) * DDIM + row];
            v.y += Zp[(size_t)(col + 1) * DDIM + row];
            v.z += Zp[(size_t)(col + 2) * DDIM + row];
            v.w += Zp[(size_t)(col + 3) * DDIM + row];
        }
        *(float4*)&C[(size_t)row * ldc + tc * 4] = v;
    }
}

// T = M*XLY + Z^T ; W = M^T*T
__global__ __launch_bounds__(256) void solve1_kernel(const float* __restrict__ Z) {
    int s = blockIdx.z, i = blockIdx.x, ct = blockIdx.y;     // (9, 4, NS)
    const float* A = g_M + (size_t)s * DD2 + (size_t)i * 128 * DDIM;
    const float* B = g_R + (size_t)s * DR + ct * 64;
    float* C = g_T + (size_t)s * DR + (size_t)i * 128 * NCOUT + ct * 64;
    const float* Zp = Z + (size_t)s * NCOUT * DDIM + (size_t)(ct * 64) * DDIM + i * 128;
    gemmK64<0>(A, DDIM, B, NCOUT, C, NCOUT, (i + 1) * 128, Zp);
}

__global__ __launch_bounds__(256) void solve2_kernel() {
    int s = blockIdx.z, i = blockIdx.x, ct = blockIdx.y;
    const float* A = g_M + (size_t)s * DD2 + (size_t)i * 128 * DDIM + i * 128;
    const float* B = g_T + (size_t)s * DR + (size_t)i * 128 * NCOUT + ct * 64;
    float* C = g_R + (size_t)s * DR + (size_t)i * 128 * NCOUT + ct * 64;
    gemmK64<1>(A, DDIM, B, NCOUT, C, NCOUT, (9 - i) * 128, nullptr);
}

// ---------------- output + reductions ----------------
__global__ __launch_bounds__(256) void finalize_kernel(const float* __restrict__ Z,
                                                       float* __restrict__ outW) {
    __shared__ float red[256];
    size_t i = (size_t)blockIdx.x * 256 + threadIdx.x;
    int d = (int)(i % DDIM);
    size_t r = i / DDIM;
    int c = (int)(r % NCOUT);
    int s = (int)(r / NCOUT);
    float w = g_R[((size_t)s * DDIM + d) * NCOUT + c];
    outW[i] = w;
    float z = Z[i];
    red[threadIdx.x] = 0.5f * z * z - 0.5f * w * w;
    __syncthreads();
    for (int off = 128; off; off >>= 1) {
        if (threadIdx.x < off) red[threadIdx.x] += red[threadIdx.x + off];
        __syncthreads();
    }
    if (threadIdx.x == 0) g_part[blockIdx.x] = red[0];
}

__global__ __launch_bounds__(256) void logpq_kernel(float* __restrict__ outL) {
    __shared__ float red[256];
    int s = blockIdx.x;
    float acc = 0.0f;
    for (int i = threadIdx.x; i < 1152; i += 256) acc += g_part[s * 1152 + i];
    red[threadIdx.x] = acc;
    __syncthreads();
    for (int off = 128; off; off >>= 1) {
        if (threadIdx.x < off) red[threadIdx.x] += red[threadIdx.x + off];
        __syncthreads();
    }
    if (threadIdx.x == 0) {
        float ld = 0.0f;
        for (int k = 0; k < NB32; k++) ld += g_logdet_part[s * NB32 + k];
        outL[s] = red[0] - 0.5f * (float)NCOUT * ld;
    }
}

// ---------------- launch ----------------
#define CHOL_SMEM (8 * 2 * 32 * 33 * (int)sizeof(float))

extern "C" void kernel_launch(void* const* d_in, const int* in_sizes, int n_in,
                              void* d_out, int out_size) {
    const float* X  = (const float*)d_in[0];
    const float* u  = (const float*)d_in[1];
    const float* lp = (const float*)d_in[2];
    const float* Z  = (const float*)d_in[3];
    float* outW = (float*)d_out;
    float* outL = outW + (size_t)NS * NCOUT * DDIM;

    cudaFuncSetAttribute(tc_gram_kernel, cudaFuncAttributeMaxDynamicSharedMemorySize, GRAM_SMEM);
    cudaFuncSetAttribute(chol_fused_kernel, cudaFuncAttributeMaxDynamicSharedMemorySize, CHOL_SMEM);

    build_patches<<<147456, 256>>>(X, lp);
    build_yt<<<8192, 256>>>(u, lp);
    zero_ms_kernel<<<NS * DD2 / 4 / 256, 256>>>();
    tc_gram_kernel<<<dim3(63, NS), 256, GRAM_SMEM>>>();

    chol_fused_kernel<<<NCTA, 256, CHOL_SMEM>>>();

    solve1_kernel<<<dim3(9, 4, NS), 256>>>(Z);
    solve2_kernel<<<dim3(9, 4, NS), 256>>>();

    finalize_kernel<<<4608, 256>>>(Z, outW);
    logpq_kernel<<<NS, 256>>>(outL);
}

// round 17
// speedup vs baseline: 1.6940x; 1.6940x over previous
#include <cuda_runtime.h>
#include <cuda_bf16.h>
#include <math.h>
#include <stdint.h>

// ---------------- problem constants ----------------
#define NS     4
#define NBATCH 32
#define NCIN   128
#define NCOUT  256
#define HH     16
#define WW     16
#define DDIM   1152
#define NPIX   256
#define NCOLS  8192
#define NB32   36          // 32-wide blocks per dim
#define DD2    (DDIM * DDIM)
#define DR     (DDIM * NCOUT)

// ---------------- scratch ----------------
__device__ __nv_bfloat16 g_Phi[(size_t)NS * DDIM * NCOLS];
__device__ __nv_bfloat16 g_Plo[(size_t)NS * DDIM * NCOLS];
__device__ __nv_bfloat16 g_Yhi[(size_t)NCOUT * NCOLS];
__device__ __nv_bfloat16 g_Ylo[(size_t)NCOUT * NCOLS];
__device__ float g_prec[(size_t)NS * DD2];
__device__ float g_M   [(size_t)NS * DD2];   // explicit block lower inverse of L (32-blocked)
__device__ float g_S   [(size_t)NS * DD2];   // substitution accumulators
__device__ float g_R   [(size_t)NS * DR];
__device__ float g_T   [(size_t)NS * DR];
__device__ float g_logdet_part[NS * NB32];
__device__ float g_part[NS * 1152];

// ---------------- helpers ----------------
__device__ __forceinline__ uint32_t smem_u32(const void* p) {
    uint32_t a;
    asm("{ .reg .u64 t; cvta.to.shared.u64 t, %1; cvt.u32.u64 %0, t; }" : "=r"(a) : "l"(p));
    return a;
}

#define CP_ASYNC16(dst, src) \
    asm volatile("cp.async.cg.shared.global [%0], [%1], 16;" :: "r"(dst), "l"(src) : "memory")
#define CP_COMMIT() asm volatile("cp.async.commit_group;" ::: "memory")
#define CP_WAIT1()  asm volatile("cp.async.wait_group 1;" ::: "memory")

#define LDMATRIX_X4(r0, r1, r2, r3, addr) \
    asm volatile("ldmatrix.sync.aligned.m8n8.x4.shared.b16 {%0,%1,%2,%3}, [%4];" \
        : "=r"(r0), "=r"(r1), "=r"(r2), "=r"(r3) : "r"(addr))

#define MMA16816(d, a, b0, b1) \
    asm volatile("mma.sync.aligned.m16n8k16.row.col.f32.bf16.bf16.f32 " \
        "{%0,%1,%2,%3}, {%4,%5,%6,%7}, {%8,%9}, {%0,%1,%2,%3};" \
        : "+f"((d)[0]), "+f"((d)[1]), "+f"((d)[2]), "+f"((d)[3]) \
        : "r"((a)[0]), "r"((a)[1]), "r"((a)[2]), "r"((a)[3]), "r"(b0), "r"(b1))

__device__ __forceinline__ uint32_t sw128(uint32_t off) {
    return off ^ ((off >> 3) & 0x70);
}

// ---------------- patch build (bf16 hi/lo) ----------------
__global__ __launch_bounds__(256) void build_patches(const float* __restrict__ X,
                                                     const float* __restrict__ lp) {
    size_t i = (size_t)blockIdx.x * 256 + threadIdx.x;
    int n = (int)(i % NCOLS);
    size_t r = i / NCOLS;
    int d = (int)(r % DDIM);
    int s = (int)(r / DDIM);
    int b = n >> 8;
    int p = n & 255;
    int y = p >> 4, x = p & 15;
    int cin = d / 9;
    int rem = d - cin * 9;
    int kh = rem / 3, kw = rem - kh * 3;
    int yy = y + kh - 1, xx = x + kw - 1;
    float v = 0.0f;
    if (yy >= 0 && yy < HH && xx >= 0 && xx < WW) {
        float sp = expf(0.5f * lp[b]);
        v = sp * X[((((size_t)s * NBATCH + b) * NCIN + cin) * HH + yy) * WW + xx];
    }
    __nv_bfloat16 hi = __float2bfloat16_rn(v);
    g_Phi[i] = hi;
    g_Plo[i] = __float2bfloat16_rn(v - __bfloat162float(hi));
}

__global__ __launch_bounds__(256) void build_yt(const float* __restrict__ u,
                                                const float* __restrict__ lp) {
    size_t i = (size_t)blockIdx.x * 256 + threadIdx.x;
    int n = (int)(i % NCOLS);
    int c = (int)(i / NCOLS);
    int b = n >> 8;
    int p = n & 255;
    float v = expf(0.5f * lp[b]) * u[((size_t)b * NCOUT + c) * NPIX + p];
    __nv_bfloat16 hi = __float2bfloat16_rn(v);
    g_Yhi[i] = hi;
    g_Ylo[i] = __float2bfloat16_rn(v - __bfloat162float(hi));
}

// zero S and M (M's untouched upper blocks must be 0 for the dense solves)
__global__ __launch_bounds__(256) void zero_ms_kernel() {
    size_t i = (size_t)blockIdx.x * 256 + threadIdx.x;
    float4 z = make_float4(0.f, 0.f, 0.f, 0.f);
    ((float4*)g_S)[i] = z;
    ((float4*)g_M)[i] = z;
}

// ---------------- warp-MMA Gram kernel (R10 config: K-chunk 64, 1 CTA/SM) ----------------
#define TILE_B 16384
#define BUF_B  65536
#define GRAM_SMEM (2 * BUF_B)

__global__ __launch_bounds__(256, 1) void tc_gram_kernel() {
    extern __shared__ char sm[];
    uint32_t smb = smem_u32(sm);
    int tid = threadIdx.x;
    int wid = tid >> 5, lid = tid & 31;
    int s = blockIdx.y;
    int t = blockIdx.x;

    const __nv_bfloat16 *Ah, *Al, *Bh, *Bl;
    float* C;
    int ldc;
    float prior;
    if (t < 45) {
        int bi = 0;
        while ((bi + 1) * (bi + 2) / 2 <= t) bi++;
        int bj = t - bi * (bi + 1) / 2;
        size_t ar = (size_t)(s * DDIM + bi * 128) * NCOLS;
        size_t br = (size_t)(s * DDIM + bj * 128) * NCOLS;
        Ah = g_Phi + ar; Al = g_Plo + ar;
        Bh = g_Phi + br; Bl = g_Plo + br;
        C = g_prec + (size_t)s * DD2 + (size_t)bi * 128 * DDIM + bj * 128;
        ldc = DDIM;
        prior = (bi == bj) ? 1.0f : 0.0f;
    } else {
        int u2 = t - 45;
        int bi = u2 >> 1, bj = u2 & 1;
        size_t ar = (size_t)(s * DDIM + bi * 128) * NCOLS;
        size_t br = (size_t)bj * 128 * NCOLS;
        Ah = g_Phi + ar; Al = g_Plo + ar;
        Bh = g_Yhi + br; Bl = g_Ylo + br;
        C = g_R + (size_t)s * DR + (size_t)bi * 128 * NCOUT + bj * 128;
        ldc = NCOUT;
        prior = 0.0f;
    }

    int lrow[4], lseg[4];
    uint32_t lsw[4];
#pragma unroll
    for (int j = 0; j < 4; j++) {
        int idx = tid + j * 256;
        lrow[j] = idx >> 3;
        lseg[j] = idx & 7;
        lsw[j] = sw128((uint32_t)(lrow[j] * 128 + lseg[j] * 16));
    }

    float acc[2][8][4];
#pragma unroll
    for (int a = 0; a < 2; a++)
#pragma unroll
        for (int b = 0; b < 8; b++)
#pragma unroll
            for (int c = 0; c < 4; c++) acc[a][b][c] = 0.0f;

    int wm = (wid >> 1) * 32;
    int wn = (wid & 1) * 64;
    int l16 = lid & 15;
    int kseg16 = (lid >> 4) * 16;

    {
#pragma unroll
        for (int arr = 0; arr < 4; arr++) {
            const __nv_bfloat16* G = (arr == 0) ? Ah : (arr == 1) ? Al : (arr == 2) ? Bh : Bl;
#pragma unroll
            for (int j = 0; j < 4; j++)
                CP_ASYNC16(smb + arr * TILE_B + lsw[j],
                           G + (size_t)lrow[j] * NCOLS + lseg[j] * 8);
        }
        CP_COMMIT();
    }

    for (int i = 0; i < 128; i++) {
        int buf = i & 1;
        if (i + 1 < 128) {
            int k0 = (i + 1) * 64;
            uint32_t bb = smb + ((i + 1) & 1) * BUF_B;
#pragma unroll
            for (int arr = 0; arr < 4; arr++) {
                const __nv_bfloat16* G = (arr == 0) ? Ah : (arr == 1) ? Al : (arr == 2) ? Bh : Bl;
#pragma unroll
                for (int j = 0; j < 4; j++)
                    CP_ASYNC16(bb + arr * TILE_B + lsw[j],
                               G + (size_t)lrow[j] * NCOLS + k0 + lseg[j] * 8);
            }
        }
        CP_COMMIT();
        CP_WAIT1();
        __syncthreads();

        uint32_t base = smb + buf * BUF_B;
#pragma unroll
        for (int ks = 0; ks < 4; ks++) {
            int kb = ks * 32 + kseg16;
            uint32_t ah[2][4], al[2][4], bh[4][4], bl[4][4];
#pragma unroll
            for (int mb = 0; mb < 2; mb++) {
                uint32_t off = sw128((uint32_t)((wm + mb * 16 + l16) * 128 + kb));
                LDMATRIX_X4(ah[mb][0], ah[mb][1], ah[mb][2], ah[mb][3], base + off);
                LDMATRIX_X4(al[mb][0], al[mb][1], al[mb][2], al[mb][3], base + TILE_B + off);
            }
#pragma unroll
            for (int nb = 0; nb < 4; nb++) {
                uint32_t off = sw128((uint32_t)((wn + nb * 16 + l16) * 128 + kb));
                LDMATRIX_X4(bh[nb][0], bh[nb][1], bh[nb][2], bh[nb][3], base + 2 * TILE_B + off);
                LDMATRIX_X4(bl[nb][0], bl[nb][1], bl[nb][2], bl[nb][3], base + 3 * TILE_B + off);
            }
#pragma unroll
            for (int mb = 0; mb < 2; mb++)
#pragma unroll
                for (int n8 = 0; n8 < 8; n8++) {
                    int nb = n8 >> 1, h = n8 & 1;
                    MMA16816(acc[mb][n8], ah[mb], bh[nb][h], bh[nb][h + 2]);
                    MMA16816(acc[mb][n8], ah[mb], bl[nb][h], bl[nb][h + 2]);
                    MMA16816(acc[mb][n8], al[mb], bh[nb][h], bh[nb][h + 2]);
                }
        }
        __syncthreads();
    }

    int tq = lid >> 2;
    int tc2 = (lid & 3) * 2;
#pragma unroll
    for (int mb = 0; mb < 2; mb++) {
#pragma unroll
        for (int n8 = 0; n8 < 8; n8++) {
            int col = wn + n8 * 8 + tc2;
            int row0 = wm + mb * 16 + tq;
            int row1 = row0 + 8;
            float c0 = acc[mb][n8][0], c1 = acc[mb][n8][1];
            float c2 = acc[mb][n8][2], c3 = acc[mb][n8][3];
            if (prior != 0.0f) {
                if (row0 == col) c0 += prior;
                if (row0 == col + 1) c1 += prior;
                if (row1 == col) c2 += prior;
                if (row1 == col + 1) c3 += prior;
            }
            *(float2*)&C[(size_t)row0 * ldc + col] = make_float2(c0, c1);
            *(float2*)&C[(size_t)row1 * ldc + col] = make_float2(c2, c3);
        }
    }
}

// ---------------- 32-blocked Cholesky via small launches ----------------

// warp-level factor + triangular inverse of a 32x32 diag block (registers + shfl)
__device__ __forceinline__ void warp_factor32(float* __restrict__ Pd,
                                              float* __restrict__ Md,
                                              float* __restrict__ ldslot, int lane) {
    int r = lane;
    float row[32];
#pragma unroll
    for (int q = 0; q < 8; q++) {
        float4 v = *((const float4*)(Pd + (size_t)r * DDIM + q * 4));
        row[q * 4 + 0] = v.x; row[q * 4 + 1] = v.y;
        row[q * 4 + 2] = v.z; row[q * 4 + 3] = v.w;
    }
    float myd = 1.0f;
#pragma unroll
    for (int j = 0; j < 32; j++) {
        float d = __shfl_sync(0xffffffffu, row[j], j);
        float ljj = sqrtf(d);
        float inv = 1.0f / ljj;
        if (r == j) myd = ljj;
        row[j] = (r == j) ? ljj : ((r > j) ? row[j] * inv : row[j]);
        float lrj = row[j];
#pragma unroll
        for (int c = j + 1; c < 32; c++) {
            float lcj = __shfl_sync(0xffffffffu, row[j], c);
            if (r >= c) row[c] -= lrj * lcj;
        }
    }
#pragma unroll
    for (int q = 0; q < 8; q++)
        *((float4*)(Pd + (size_t)r * DDIM + q * 4)) =
            make_float4(row[q * 4], row[q * 4 + 1], row[q * 4 + 2], row[q * 4 + 3]);
    // triangular inverse: lane = column c
    int c = r;
    float x[32];
#pragma unroll
    for (int i = 0; i < 32; i++) {
        float a2 = (i == c) ? 1.0f : 0.0f;
#pragma unroll
        for (int tt = 0; tt < i; tt++) {
            float lit = __shfl_sync(0xffffffffu, row[tt], i);
            a2 -= lit * x[tt];
        }
        float lii = __shfl_sync(0xffffffffu, row[i], i);
        x[i] = a2 * (1.0f / lii);
    }
#pragma unroll
    for (int i = 0; i < 32; i++)
        Md[(size_t)i * DDIM + c] = x[i];
    float lv = 2.0f * logf(myd);
#pragma unroll
    for (int o = 16; o; o >>= 1) lv += __shfl_xor_sync(0xffffffffu, lv, o);
    if (lane == 0) *ldslot = lv;
}

// warp-level 32x32x32 GEMM: C = alpha * A @ opB(B) (+ C if beta); ld = DDIM everywhere.
__device__ __forceinline__ void wgemm32(const float* __restrict__ A,
                                        const float* __restrict__ B,
                                        float* __restrict__ C,
                                        int TB, float alpha, int beta,
                                        float* As_, float* Bs_, int lane) {
    {
        const float4* ar = (const float4*)(A + (size_t)lane * DDIM);
        const float4* br = (const float4*)(B + (size_t)lane * DDIM);
#pragma unroll
        for (int q = 0; q < 8; q++) {
            float4 va = ar[q];
            float4 vb = br[q];
            As_[lane * 33 + q * 4 + 0] = va.x; As_[lane * 33 + q * 4 + 1] = va.y;
            As_[lane * 33 + q * 4 + 2] = va.z; As_[lane * 33 + q * 4 + 3] = va.w;
            Bs_[lane * 33 + q * 4 + 0] = vb.x; Bs_[lane * 33 + q * 4 + 1] = vb.y;
            Bs_[lane * 33 + q * 4 + 2] = vb.z; Bs_[lane * 33 + q * 4 + 3] = vb.w;
        }
    }
    __syncwarp();
    float acc[32];
#pragma unroll
    for (int r = 0; r < 32; r++) acc[r] = 0.0f;
    if (TB) {
#pragma unroll 4
        for (int k = 0; k < 32; k++) {
            float bv = Bs_[lane * 33 + k];          // B[c][k]  (B^T)
#pragma unroll
            for (int r = 0; r < 32; r++)
                acc[r] = fmaf(As_[r * 33 + k], bv, acc[r]);
        }
    } else {
#pragma unroll 4
        for (int k = 0; k < 32; k++) {
            float bv = Bs_[k * 33 + lane];          // B[k][c]
#pragma unroll
            for (int r = 0; r < 32; r++)
                acc[r] = fmaf(As_[r * 33 + k], bv, acc[r]);
        }
    }
#pragma unroll 4
    for (int r = 0; r < 32; r++) {
        float v = alpha * acc[r];
        if (beta) v += C[(size_t)r * DDIM + lane];
        C[(size_t)r * DDIM + lane] = v;
    }
    __syncwarp();
}

// A0: factor block (0,0) for all s
__global__ __launch_bounds__(128) void cholA0_kernel() {
    int wid = threadIdx.x >> 5, lane = threadIdx.x & 31;
    int s = wid;
    warp_factor32(g_prec + (size_t)s * DD2, g_M + (size_t)s * DD2,
                  &g_logdet_part[s * NB32], lane);
}

// B(t): TRSM panels (rem tiles) + M column t (t tiles); 35 tiles per s
__global__ __launch_bounds__(256) void cholB_kernel(int t) {
    extern __shared__ float shm[];
    int tid = threadIdx.x, wid = tid >> 5, lane = tid & 31;
    float* As = shm + wid * 2 * 32 * 33;
    float* Bs = As + 32 * 33;
    int tile = blockIdx.x * 8 + wid;
    if (tile >= NS * 35) return;
    int s = tile / 35;
    int j = tile % 35;
    int rem = NB32 - 1 - t;
    float* P = g_prec + (size_t)s * DD2;
    float* M = g_M + (size_t)s * DD2;
    const float* Mtt = M + (size_t)(t * 32) * DDIM + t * 32;
    if (j < rem) {
        int i = t + 1 + j;
        float* Pit = P + (size_t)(i * 32) * DDIM + t * 32;
        wgemm32(Pit, Mtt, Pit, 1, 1.0f, 0, As, Bs, lane);   // L_it = P_it @ Mtt^T
    } else {
        int k = j - rem;  // 0..t-1
        const float* Stk = g_S + (size_t)s * DD2 + (size_t)(t * 32) * DDIM + k * 32;
        float* Mtk = M + (size_t)(t * 32) * DDIM + k * 32;
        wgemm32(Mtt, Stk, Mtk, 0, -1.0f, 0, As, Bs, lane);  // M_tk = -Mtt @ S_tk
    }
}

// C(t): SYRK trailing + S accumulation; warp with m==0 also factors diag (t+1) afterwards
__global__ __launch_bounds__(256) void cholC_kernel(int t) {
    extern __shared__ float shm[];
    int tid = threadIdx.x, wid = tid >> 5, lane = tid & 31;
    float* As = shm + wid * 2 * 32 * 33;
    float* Bs = As + 32 * 33;
    int rem = NB32 - 1 - t;
    int ntri = rem * (rem + 1) / 2;
    int per_s = ntri + rem * (t + 1);
    int tile = blockIdx.x * 8 + wid;
    if (tile >= NS * per_s) return;
    int s = tile / per_s;
    int m = tile % per_s;
    float* P = g_prec + (size_t)s * DD2;
    if (m < ntri) {
        int a = 0;
        while ((a + 1) * (a + 2) / 2 <= m) a++;
        int b = m - a * (a + 1) / 2;
        int i = t + 1 + a, j2 = t + 1 + b;
        wgemm32(P + (size_t)(i * 32) * DDIM + t * 32,
                P + (size_t)(j2 * 32) * DDIM + t * 32,
                P + (size_t)(i * 32) * DDIM + j2 * 32,
                1, -1.0f, 1, As, Bs, lane);                 // P_ij -= L_it @ L_jt^T
        if (m == 0) {
            // diag (t+1,t+1) now fully updated: factor it in-warp
            __threadfence_block();
            __syncwarp();
            warp_factor32(P + (size_t)((t + 1) * 32) * DDIM + (t + 1) * 32,
                          g_M + (size_t)s * DD2 + (size_t)((t + 1) * 32) * DDIM + (t + 1) * 32,
                          &g_logdet_part[s * NB32 + t + 1], lane);
        }
    } else {
        int e = m - ntri;
        int i = t + 1 + e / (t + 1);
        int k = e % (t + 1);
        wgemm32(P + (size_t)(i * 32) * DDIM + t * 32,
                g_M + (size_t)s * DD2 + (size_t)(t * 32) * DDIM + k * 32,
                g_S + (size_t)s * DD2 + (size_t)(i * 32) * DDIM + k * 32,
                0, 1.0f, 1, As, Bs, lane);                  // S_ik += L_it @ M_tk
    }
}

// ---------------- fp32 128x64 GEMM for the dense solves ----------------
template <int TA>
__device__ __forceinline__ void gemmK64(const float* __restrict__ A, int lda,
                                        const float* __restrict__ Bp, int ldb,
                                        float* __restrict__ C, int ldc,
                                        int Kdim, const float* __restrict__ Zp) {
    __shared__ float As[16][128];
    __shared__ float Bs[16][64];
    float acc[8][4];
#pragma unroll
    for (int a = 0; a < 8; a++)
#pragma unroll
        for (int b = 0; b < 4; b++) acc[a][b] = 0.0f;
    int tid = threadIdx.x;
    int tr = tid >> 4, tc = tid & 15;

    for (int k0 = 0; k0 < Kdim; k0 += 16) {
#pragma unroll
        for (int q = 0; q < 2; q++) {
            int idx = tid + q * 256;
            if (TA) {
                int kk = idx >> 5, m4 = (idx & 31) << 2;
                float4 v = *(const float4*)&A[(size_t)(k0 + kk) * lda + m4];
                *(float4*)&As[kk][m4] = v;
            } else {
                int rr = idx >> 2, c4 = (idx & 3) << 2;
                float4 v = *(const float4*)&A[(size_t)rr * lda + k0 + c4];
                As[c4 + 0][rr] = v.x; As[c4 + 1][rr] = v.y;
                As[c4 + 2][rr] = v.z; As[c4 + 3][rr] = v.w;
            }
        }
        {
            int kk = tid >> 4, n4 = (tid & 15) << 2;
            float4 v = *(const float4*)&Bp[(size_t)(k0 + kk) * ldb + n4];
            *(float4*)&Bs[kk][n4] = v;
        }
        __syncthreads();
#pragma unroll
        for (int kk = 0; kk < 16; kk++) {
            float ra[8], rb[4];
            *(float4*)&ra[0] = *(const float4*)&As[kk][tr * 8];
            *(float4*)&ra[4] = *(const float4*)&As[kk][tr * 8 + 4];
            *(float4*)&rb[0] = *(const float4*)&Bs[kk][tc * 4];
#pragma unroll
            for (int a = 0; a < 8; a++)
#pragma unroll
                for (int b = 0; b < 4; b++)
                    acc[a][b] = fmaf(ra[a], rb[b], acc[a][b]);
        }
        __syncthreads();
    }
#pragma unroll
    for (int a = 0; a < 8; a++) {
        int row = tr * 8 + a;
        float4 v = make_float4(acc[a][0], acc[a][1], acc[a][2], acc[a][3]);
        if (Zp) {
            int col = tc * 4;
            v.x += Zp[(size_t)(col + 0) * DDIM + row];
            v.y += Zp[(size_t)(col + 1) * DDIM + row];
            v.z += Zp[(size_t)(col + 2) * DDIM + row];
            v.w += Zp[(size_t)(col + 3) * DDIM + row];
        }
        *(float4*)&C[(size_t)row * ldc + tc * 4] = v;
    }
}

// T = M*XLY + Z^T ; W = M^T*T
__global__ __launch_bounds__(256) void solve1_kernel(const float* __restrict__ Z) {
    int s = blockIdx.z, i = blockIdx.x, ct = blockIdx.y;     // (9, 4, NS)
    const float* A = g_M + (size_t)s * DD2 + (size_t)i * 128 * DDIM;
    const float* B = g_R + (size_t)s * DR + ct * 64;
    float* C = g_T + (size_t)s * DR + (size_t)i * 128 * NCOUT + ct * 64;
    const float* Zp = Z + (size_t)s * NCOUT * DDIM + (size_t)(ct * 64) * DDIM + i * 128;
    gemmK64<0>(A, DDIM, B, NCOUT, C, NCOUT, (i + 1) * 128, Zp);
}

__global__ __launch_bounds__(256) void solve2_kernel() {
    int s = blockIdx.z, i = blockIdx.x, ct = blockIdx.y;
    const float* A = g_M + (size_t)s * DD2 + (size_t)i * 128 * DDIM + i * 128;
    const float* B = g_T + (size_t)s * DR + (size_t)i * 128 * NCOUT + ct * 64;
    float* C = g_R + (size_t)s * DR + (size_t)i * 128 * NCOUT + ct * 64;
    gemmK64<1>(A, DDIM, B, NCOUT, C, NCOUT, (9 - i) * 128, nullptr);
}

// ---------------- output + reductions ----------------
__global__ __launch_bounds__(256) void finalize_kernel(const float* __restrict__ Z,
                                                       float* __restrict__ outW) {
    __shared__ float red[256];
    size_t i = (size_t)blockIdx.x * 256 + threadIdx.x;
    int d = (int)(i % DDIM);
    size_t r = i / DDIM;
    int c = (int)(r % NCOUT);
    int s = (int)(r / NCOUT);
    float w = g_R[((size_t)s * DDIM + d) * NCOUT + c];
    outW[i] = w;
    float z = Z[i];
    red[threadIdx.x] = 0.5f * z * z - 0.5f * w * w;
    __syncthreads();
    for (int off = 128; off; off >>= 1) {
        if (threadIdx.x < off) red[threadIdx.x] += red[threadIdx.x + off];
        __syncthreads();
    }
    if (threadIdx.x == 0) g_part[blockIdx.x] = red[0];
}

__global__ __launch_bounds__(256) void logpq_kernel(float* __restrict__ outL) {
    __shared__ float red[256];
    int s = blockIdx.x;
    float acc = 0.0f;
    for (int i = threadIdx.x; i < 1152; i += 256) acc += g_part[s * 1152 + i];
    red[threadIdx.x] = acc;
    __syncthreads();
    for (int off = 128; off; off >>= 1) {
        if (threadIdx.x < off) red[threadIdx.x] += red[threadIdx.x + off];
        __syncthreads();
    }
    if (threadIdx.x == 0) {
        float ld = 0.0f;
        for (int k = 0; k < NB32; k++) ld += g_logdet_part[s * NB32 + k];
        outL[s] = red[0] - 0.5f * (float)NCOUT * ld;
    }
}

// ---------------- launch ----------------
#define CHOL_SMEM (8 * 2 * 32 * 33 * (int)sizeof(float))

extern "C" void kernel_launch(void* const* d_in, const int* in_sizes, int n_in,
                              void* d_out, int out_size) {
    const float* X  = (const float*)d_in[0];
    const float* u  = (const float*)d_in[1];
    const float* lp = (const float*)d_in[2];
    const float* Z  = (const float*)d_in[3];
    float* outW = (float*)d_out;
    float* outL = outW + (size_t)NS * NCOUT * DDIM;

    cudaFuncSetAttribute(tc_gram_kernel, cudaFuncAttributeMaxDynamicSharedMemorySize, GRAM_SMEM);
    cudaFuncSetAttribute(cholB_kernel, cudaFuncAttributeMaxDynamicSharedMemorySize, CHOL_SMEM);
    cudaFuncSetAttribute(cholC_kernel, cudaFuncAttributeMaxDynamicSharedMemorySize, CHOL_SMEM);

    build_patches<<<147456, 256>>>(X, lp);
    build_yt<<<8192, 256>>>(u, lp);
    zero_ms_kernel<<<NS * DD2 / 4 / 256, 256>>>();
    tc_gram_kernel<<<dim3(63, NS), 256, GRAM_SMEM>>>();

    cholA0_kernel<<<1, 128>>>();
    for (int t = 0; t < NB32; t++) {
        cholB_kernel<<<(NS * 35 + 7) / 8, 256, CHOL_SMEM>>>(t);
        int rem = NB32 - 1 - t;
        if (rem > 0) {
            int per_s = rem * (rem + 1) / 2 + rem * (t + 1);
            int nw = NS * per_s;
            cholC_kernel<<<(nw + 7) / 8, 256, CHOL_SMEM>>>(t);
        }
    }

    solve1_kernel<<<dim3(9, 4, NS), 256>>>(Z);
    solve2_kernel<<<dim3(9, 4, NS), 256>>>();

    finalize_kernel<<<4608, 256>>>(Z, outW);
    logpq_kernel<<<NS, 256>>>(outL);
}